// round 13
// baseline (speedup 1.0000x reference)
#include <cuda_runtime.h>
#include <cstdint>

// GlobalFilter: y = irfft(rfft(x, axis=-1) * w, n=10, axis=-1)
// x: [B, DIM, 10] f32, w: [DIM, 6, 2] f32 -> y: [B, DIM, 10] f32
// R13: champion R8 structure (warp-autonomous 64-row sub-tiles, zero block
// barriers, cp.async in / __stcs out) with THREADS 256 -> 128: same per-warp
// schedule, 2x more independent CTAs for finer wave quantization and more
// cross-SM warp de-phasing. Per-warp SASS identical to the 102.0us champion.

#define THREADS 128
#define WARPS 4
#define WARP_ROWS 64
#define ROWS_PER_BLOCK (WARPS * WARP_ROWS)   // 256
#define NPTS 10
#define WARP_ELEMS (WARP_ROWS * NPTS)        // 640 floats = 2560 B

__host__ __device__ constexpr float ctC(int j) {
    const float t[10] = {1.0f, 0.80901699437494745f, 0.30901699437494745f,
                         -0.30901699437494745f, -0.80901699437494745f, -1.0f,
                         -0.80901699437494745f, -0.30901699437494745f,
                         0.30901699437494745f, 0.80901699437494745f};
    return t[j % 10];
}
__host__ __device__ constexpr float ctS(int j) {
    const float t[10] = {0.0f, 0.58778525229247314f, 0.95105651629515353f,
                         0.95105651629515353f, 0.58778525229247314f, 0.0f,
                         -0.58778525229247314f, -0.95105651629515353f,
                         -0.95105651629515353f, -0.58778525229247314f};
    return t[j % 10];
}

__device__ __forceinline__ void cp_async16(uint32_t saddr, const void* gptr) {
    asm volatile("cp.async.cg.shared.global [%0], [%1], 16;"
                 :: "r"(saddr), "l"(gptr));
}
#define CPA_COMMIT() asm volatile("cp.async.commit_group;" ::: "memory")
#define CPA_WAIT0()  asm volatile("cp.async.wait_group 0;" ::: "memory")

// core 10-point filtered round-trip: xv -> yv
__device__ __forceinline__ void dft10(const float xv[NPTS], float yv[NPTS],
                                      float4 w0, float4 w1, float4 w2)
{
    float u[5], v[5];
    #pragma unroll
    for (int s = 0; s < 5; ++s) {
        u[s] = xv[s] + xv[s + 5];
        v[s] = xv[s] - xv[s + 5];
    }
    float Xr0 = u[0] + u[1] + u[2] + u[3] + u[4];
    float Xr2 = u[0], Xi2 = 0.f, Xr4 = u[0], Xi4 = 0.f;
    #pragma unroll
    for (int s = 1; s < 5; ++s) {
        Xr2 += ctC(2 * s) * u[s];  Xi2 -= ctS(2 * s) * u[s];
        Xr4 += ctC(4 * s) * u[s];  Xi4 -= ctS(4 * s) * u[s];
    }
    float Xr1 = v[0], Xi1 = 0.f, Xr3 = v[0], Xi3 = 0.f;
    #pragma unroll
    for (int s = 1; s < 5; ++s) {
        Xr1 += ctC(1 * s) * v[s];  Xi1 -= ctS(1 * s) * v[s];
        Xr3 += ctC(3 * s) * v[s];  Xi3 -= ctS(3 * s) * v[s];
    }
    float Xr5 = v[0] - v[1] + v[2] - v[3] + v[4];

    const float a1 = w0.z, b1 = w0.w;
    const float a2 = w1.x, b2 = w1.y;
    const float a3 = w1.z, b3 = w1.w;
    const float a4 = w2.x, b4 = w2.y;
    const float Zr0 = 0.1f * (Xr0 * w0.x);
    const float Zr5 = 0.1f * (Xr5 * w2.z);
    const float zr1 = 0.2f * (Xr1 * a1 - Xi1 * b1);
    const float zi1 = 0.2f * (Xr1 * b1 + Xi1 * a1);
    const float zr2 = 0.2f * (Xr2 * a2 - Xi2 * b2);
    const float zi2 = 0.2f * (Xr2 * b2 + Xi2 * a2);
    const float zr3 = 0.2f * (Xr3 * a3 - Xi3 * b3);
    const float zi3 = 0.2f * (Xr3 * b3 + Xi3 * a3);
    const float zr4 = 0.2f * (Xr4 * a4 - Xi4 * b4);
    const float zi4 = 0.2f * (Xr4 * b4 + Xi4 * a4);

    #pragma unroll
    for (int t = 0; t < 5; ++t) {
        float E = Zr0
                + zr2 * ctC(2 * t) - zi2 * ctS(2 * t)
                + zr4 * ctC(4 * t) - zi4 * ctS(4 * t);
        float O = ((t & 1) ? -Zr5 : Zr5)
                + zr1 * ctC(t)     - zi1 * ctS(t)
                + zr3 * ctC(3 * t) - zi3 * ctS(3 * t);
        yv[t]     = E + O;
        yv[t + 5] = E - O;
    }
}

// process one row stored at sx[ridx*10 .. ridx*10+10)
__device__ __forceinline__ void process_row(float* sx, int ridx,
                                            const float* __restrict__ w, int d)
{
    const float4* wp = reinterpret_cast<const float4*>(w + d * 12);
    const float4 w0 = wp[0];
    const float4 w1 = wp[1];
    const float4 w2 = wp[2];

    float xv[NPTS], yv[NPTS];
    const float2* s2 = reinterpret_cast<const float2*>(sx);
    #pragma unroll
    for (int i = 0; i < 5; ++i) {
        float2 p = s2[ridx * 5 + i];
        xv[2 * i] = p.x; xv[2 * i + 1] = p.y;
    }
    dft10(xv, yv, w0, w1, w2);
    float2* s2w = reinterpret_cast<float2*>(sx);
    #pragma unroll
    for (int i = 0; i < 5; ++i) {
        float2 p; p.x = yv[2 * i]; p.y = yv[2 * i + 1];
        s2w[ridx * 5 + i] = p;
    }
}

__global__ __launch_bounds__(THREADS)
void global_filter_kernel(const float* __restrict__ x,
                          const float* __restrict__ w,
                          float* __restrict__ y,
                          int n_rows, int dim, int dim_mask)
{
    __shared__ float sx[ROWS_PER_BLOCK * NPTS];   // 10240 B

    const int tid  = threadIdx.x;
    const int wid  = tid >> 5;
    const int lane = tid & 31;
    const int row0 = blockIdx.x * ROWS_PER_BLOCK;
    const int rows_here = min(ROWS_PER_BLOCK, n_rows - row0);

    if (rows_here == ROWS_PER_BLOCK) {
        // ---- warp-autonomous path: no block barriers ----
        const int wrow0 = row0 + wid * WARP_ROWS;        // warp's first row
        float* ws = sx + wid * WARP_ELEMS;               // warp's smem region
        const uint32_t wsb = (uint32_t)__cvta_generic_to_shared(ws);

        // stage in: 5 cp.async per lane (warp covers 160 float4 = 2560 B)
        const float4* g = reinterpret_cast<const float4*>(x) +
                          (long long)wrow0 * NPTS / 4;
        #pragma unroll
        for (int i = 0; i < 5; ++i)
            cp_async16(wsb + (uint32_t)(lane + i * 32) * 16u,
                       g + lane + i * 32);
        CPA_COMMIT();
        CPA_WAIT0();
        __syncwarp();

        // compute: 2 rows per lane (rows lane and lane+32 within warp tile)
        const int rA = wrow0 + lane;
        const int rB = rA + 32;
        const int dA = (dim_mask >= 0) ? (rA & dim_mask) : (rA % dim);
        const int dB = (dim_mask >= 0) ? (rB & dim_mask) : (rB % dim);
        process_row(ws, lane,      w, dA);
        process_row(ws, lane + 32, w, dB);
        __syncwarp();

        // stage out: streaming float4 stores
        float4* gy = reinterpret_cast<float4*>(y) +
                     (long long)wrow0 * NPTS / 4;
        const float4* s4 = reinterpret_cast<const float4*>(ws);
        #pragma unroll
        for (int i = 0; i < 5; ++i)
            __stcs(gy + lane + i * 32, s4[lane + i * 32]);
    } else {
        // ---- tail block: straight from global, scalar ----
        for (int rr = tid; rr < rows_here; rr += THREADS) {
            const int row = row0 + rr;
            const long long rb = (long long)row * NPTS;
            const int d = (dim_mask >= 0) ? (row & dim_mask) : (row % dim);
            const float4* wp = reinterpret_cast<const float4*>(w + d * 12);
            float xv[NPTS], yv[NPTS];
            #pragma unroll
            for (int i = 0; i < NPTS; ++i) xv[i] = x[rb + i];
            dft10(xv, yv, wp[0], wp[1], wp[2]);
            #pragma unroll
            for (int i = 0; i < NPTS; ++i) y[rb + i] = yv[i];
        }
    }
}

extern "C" void kernel_launch(void* const* d_in, const int* in_sizes, int n_in,
                              void* d_out, int out_size)
{
    const float* x = (const float*)d_in[0];
    const float* w = (const float*)d_in[1];
    float* y = (float*)d_out;

    const int n_rows = in_sizes[0] / NPTS;       // B * DIM
    const int dim    = in_sizes[1] / 12;         // DIM
    const int dim_mask = ((dim & (dim - 1)) == 0) ? (dim - 1) : -1;

    const int blocks = (n_rows + ROWS_PER_BLOCK - 1) / ROWS_PER_BLOCK;
    global_filter_kernel<<<blocks, THREADS>>>(x, w, y, n_rows, dim, dim_mask);
}

// round 14
// speedup vs baseline: 1.0060x; 1.0060x over previous
#include <cuda_runtime.h>
#include <cstdint>

// GlobalFilter: y = irfft(rfft(x, axis=-1) * w, n=10, axis=-1)
// x: [B, DIM, 10] f32, w: [DIM, 6, 2] f32 -> y: [B, DIM, 10] f32
// R14 (FINAL candidate): champion R8 structure (warp-autonomous 64-row
// sub-tiles, zero block barriers, cp.async in / __stcs out) with the
// L2::256B prefetch hint on the stage-in cp.async: warp bursts are 2560
// contiguous bytes, so granule-sized L2 fetches let the DRAM controller
// schedule 256B transactions instead of independent 32B sectors.
// Champion baseline: 102.0us timed / 96.4us kernel, DRAM 80.6%.

#define THREADS 256
#define WARPS 8
#define WARP_ROWS 64
#define ROWS_PER_BLOCK (WARPS * WARP_ROWS)   // 512
#define NPTS 10
#define WARP_ELEMS (WARP_ROWS * NPTS)        // 640 floats = 2560 B

__host__ __device__ constexpr float ctC(int j) {
    const float t[10] = {1.0f, 0.80901699437494745f, 0.30901699437494745f,
                         -0.30901699437494745f, -0.80901699437494745f, -1.0f,
                         -0.80901699437494745f, -0.30901699437494745f,
                         0.30901699437494745f, 0.80901699437494745f};
    return t[j % 10];
}
__host__ __device__ constexpr float ctS(int j) {
    const float t[10] = {0.0f, 0.58778525229247314f, 0.95105651629515353f,
                         0.95105651629515353f, 0.58778525229247314f, 0.0f,
                         -0.58778525229247314f, -0.95105651629515353f,
                         -0.95105651629515353f, -0.58778525229247314f};
    return t[j % 10];
}

__device__ __forceinline__ void cp_async16_l2_256(uint32_t saddr, const void* gptr) {
    asm volatile("cp.async.cg.shared.global.L2::256B [%0], [%1], 16;"
                 :: "r"(saddr), "l"(gptr));
}
#define CPA_COMMIT() asm volatile("cp.async.commit_group;" ::: "memory")
#define CPA_WAIT0()  asm volatile("cp.async.wait_group 0;" ::: "memory")

// core 10-point filtered round-trip: xv -> yv
__device__ __forceinline__ void dft10(const float xv[NPTS], float yv[NPTS],
                                      float4 w0, float4 w1, float4 w2)
{
    float u[5], v[5];
    #pragma unroll
    for (int s = 0; s < 5; ++s) {
        u[s] = xv[s] + xv[s + 5];
        v[s] = xv[s] - xv[s + 5];
    }
    float Xr0 = u[0] + u[1] + u[2] + u[3] + u[4];
    float Xr2 = u[0], Xi2 = 0.f, Xr4 = u[0], Xi4 = 0.f;
    #pragma unroll
    for (int s = 1; s < 5; ++s) {
        Xr2 += ctC(2 * s) * u[s];  Xi2 -= ctS(2 * s) * u[s];
        Xr4 += ctC(4 * s) * u[s];  Xi4 -= ctS(4 * s) * u[s];
    }
    float Xr1 = v[0], Xi1 = 0.f, Xr3 = v[0], Xi3 = 0.f;
    #pragma unroll
    for (int s = 1; s < 5; ++s) {
        Xr1 += ctC(1 * s) * v[s];  Xi1 -= ctS(1 * s) * v[s];
        Xr3 += ctC(3 * s) * v[s];  Xi3 -= ctS(3 * s) * v[s];
    }
    float Xr5 = v[0] - v[1] + v[2] - v[3] + v[4];

    const float a1 = w0.z, b1 = w0.w;
    const float a2 = w1.x, b2 = w1.y;
    const float a3 = w1.z, b3 = w1.w;
    const float a4 = w2.x, b4 = w2.y;
    const float Zr0 = 0.1f * (Xr0 * w0.x);
    const float Zr5 = 0.1f * (Xr5 * w2.z);
    const float zr1 = 0.2f * (Xr1 * a1 - Xi1 * b1);
    const float zi1 = 0.2f * (Xr1 * b1 + Xi1 * a1);
    const float zr2 = 0.2f * (Xr2 * a2 - Xi2 * b2);
    const float zi2 = 0.2f * (Xr2 * b2 + Xi2 * a2);
    const float zr3 = 0.2f * (Xr3 * a3 - Xi3 * b3);
    const float zi3 = 0.2f * (Xr3 * b3 + Xi3 * a3);
    const float zr4 = 0.2f * (Xr4 * a4 - Xi4 * b4);
    const float zi4 = 0.2f * (Xr4 * b4 + Xi4 * a4);

    #pragma unroll
    for (int t = 0; t < 5; ++t) {
        float E = Zr0
                + zr2 * ctC(2 * t) - zi2 * ctS(2 * t)
                + zr4 * ctC(4 * t) - zi4 * ctS(4 * t);
        float O = ((t & 1) ? -Zr5 : Zr5)
                + zr1 * ctC(t)     - zi1 * ctS(t)
                + zr3 * ctC(3 * t) - zi3 * ctS(3 * t);
        yv[t]     = E + O;
        yv[t + 5] = E - O;
    }
}

// process one row stored at sx[ridx*10 .. ridx*10+10)
__device__ __forceinline__ void process_row(float* sx, int ridx,
                                            const float* __restrict__ w, int d)
{
    const float4* wp = reinterpret_cast<const float4*>(w + d * 12);
    const float4 w0 = wp[0];
    const float4 w1 = wp[1];
    const float4 w2 = wp[2];

    float xv[NPTS], yv[NPTS];
    const float2* s2 = reinterpret_cast<const float2*>(sx);
    #pragma unroll
    for (int i = 0; i < 5; ++i) {
        float2 p = s2[ridx * 5 + i];
        xv[2 * i] = p.x; xv[2 * i + 1] = p.y;
    }
    dft10(xv, yv, w0, w1, w2);
    float2* s2w = reinterpret_cast<float2*>(sx);
    #pragma unroll
    for (int i = 0; i < 5; ++i) {
        float2 p; p.x = yv[2 * i]; p.y = yv[2 * i + 1];
        s2w[ridx * 5 + i] = p;
    }
}

__global__ __launch_bounds__(THREADS)
void global_filter_kernel(const float* __restrict__ x,
                          const float* __restrict__ w,
                          float* __restrict__ y,
                          int n_rows, int dim, int dim_mask)
{
    __shared__ float sx[ROWS_PER_BLOCK * NPTS];   // 20480 B

    const int tid  = threadIdx.x;
    const int wid  = tid >> 5;
    const int lane = tid & 31;
    const int row0 = blockIdx.x * ROWS_PER_BLOCK;
    const int rows_here = min(ROWS_PER_BLOCK, n_rows - row0);

    if (rows_here == ROWS_PER_BLOCK) {
        // ---- warp-autonomous path: no block barriers ----
        const int wrow0 = row0 + wid * WARP_ROWS;        // warp's first row
        float* ws = sx + wid * WARP_ELEMS;               // warp's smem region
        const uint32_t wsb = (uint32_t)__cvta_generic_to_shared(ws);

        // stage in: 5 cp.async per lane with 256B L2 granule hint
        const float4* g = reinterpret_cast<const float4*>(x) +
                          (long long)wrow0 * NPTS / 4;
        #pragma unroll
        for (int i = 0; i < 5; ++i)
            cp_async16_l2_256(wsb + (uint32_t)(lane + i * 32) * 16u,
                              g + lane + i * 32);
        CPA_COMMIT();
        CPA_WAIT0();
        __syncwarp();

        // compute: 2 rows per lane (rows lane and lane+32 within warp tile)
        const int rA = wrow0 + lane;
        const int rB = rA + 32;
        const int dA = (dim_mask >= 0) ? (rA & dim_mask) : (rA % dim);
        const int dB = (dim_mask >= 0) ? (rB & dim_mask) : (rB % dim);
        process_row(ws, lane,      w, dA);
        process_row(ws, lane + 32, w, dB);
        __syncwarp();

        // stage out: streaming float4 stores
        float4* gy = reinterpret_cast<float4*>(y) +
                     (long long)wrow0 * NPTS / 4;
        const float4* s4 = reinterpret_cast<const float4*>(ws);
        #pragma unroll
        for (int i = 0; i < 5; ++i)
            __stcs(gy + lane + i * 32, s4[lane + i * 32]);
    } else {
        // ---- tail block: straight from global, scalar ----
        for (int rr = tid; rr < rows_here; rr += THREADS) {
            const int row = row0 + rr;
            const long long rb = (long long)row * NPTS;
            const int d = (dim_mask >= 0) ? (row & dim_mask) : (row % dim);
            const float4* wp = reinterpret_cast<const float4*>(w + d * 12);
            float xv[NPTS], yv[NPTS];
            #pragma unroll
            for (int i = 0; i < NPTS; ++i) xv[i] = x[rb + i];
            dft10(xv, yv, wp[0], wp[1], wp[2]);
            #pragma unroll
            for (int i = 0; i < NPTS; ++i) y[rb + i] = yv[i];
        }
    }
}

extern "C" void kernel_launch(void* const* d_in, const int* in_sizes, int n_in,
                              void* d_out, int out_size)
{
    const float* x = (const float*)d_in[0];
    const float* w = (const float*)d_in[1];
    float* y = (float*)d_out;

    const int n_rows = in_sizes[0] / NPTS;       // B * DIM
    const int dim    = in_sizes[1] / 12;         // DIM
    const int dim_mask = ((dim & (dim - 1)) == 0) ? (dim - 1) : -1;

    const int blocks = (n_rows + ROWS_PER_BLOCK - 1) / ROWS_PER_BLOCK;
    global_filter_kernel<<<blocks, THREADS>>>(x, w, y, n_rows, dim, dim_mask);
}

// round 15
// speedup vs baseline: 1.0165x; 1.0105x over previous
#include <cuda_runtime.h>
#include <cstdint>

// GlobalFilter: y = irfft(rfft(x, axis=-1) * w, n=10, axis=-1)
// x: [B, DIM, 10] f32, w: [DIM, 6, 2] f32 -> y: [B, DIM, 10] f32
// R15 (FINAL): champion warp-autonomous structure (64-row sub-tiles, zero
// block barriers, cp.async in / __stcs out) + full streaming cache policy:
// reads carry L2::evict_first cache-hint + L2::256B granule hint; writes
// are evict-first (__stcs). Both streams are touch-once, so L2 acts as a
// pure staging FIFO. Baseline: 101.9us timed / 96.8us kernel, DRAM 80.2%.

#define THREADS 256
#define WARPS 8
#define WARP_ROWS 64
#define ROWS_PER_BLOCK (WARPS * WARP_ROWS)   // 512
#define NPTS 10
#define WARP_ELEMS (WARP_ROWS * NPTS)        // 640 floats = 2560 B

__host__ __device__ constexpr float ctC(int j) {
    const float t[10] = {1.0f, 0.80901699437494745f, 0.30901699437494745f,
                         -0.30901699437494745f, -0.80901699437494745f, -1.0f,
                         -0.80901699437494745f, -0.30901699437494745f,
                         0.30901699437494745f, 0.80901699437494745f};
    return t[j % 10];
}
__host__ __device__ constexpr float ctS(int j) {
    const float t[10] = {0.0f, 0.58778525229247314f, 0.95105651629515353f,
                         0.95105651629515353f, 0.58778525229247314f, 0.0f,
                         -0.58778525229247314f, -0.95105651629515353f,
                         -0.95105651629515353f, -0.58778525229247314f};
    return t[j % 10];
}

// evict_first policy for the streaming read (touch-once data)
__device__ __forceinline__ uint64_t make_evict_first_policy() {
    uint64_t pol;
    asm volatile("createpolicy.fractional.L2::evict_first.b64 %0, 1.0;"
                 : "=l"(pol));
    return pol;
}

__device__ __forceinline__ void cp_async16_stream(uint32_t saddr,
                                                  const void* gptr,
                                                  uint64_t pol) {
    asm volatile(
        "cp.async.cg.shared.global.L2::cache_hint.L2::256B [%0], [%1], 16, %2;"
        :: "r"(saddr), "l"(gptr), "l"(pol));
}
#define CPA_COMMIT() asm volatile("cp.async.commit_group;" ::: "memory")
#define CPA_WAIT0()  asm volatile("cp.async.wait_group 0;" ::: "memory")

// core 10-point filtered round-trip: xv -> yv
__device__ __forceinline__ void dft10(const float xv[NPTS], float yv[NPTS],
                                      float4 w0, float4 w1, float4 w2)
{
    float u[5], v[5];
    #pragma unroll
    for (int s = 0; s < 5; ++s) {
        u[s] = xv[s] + xv[s + 5];
        v[s] = xv[s] - xv[s + 5];
    }
    float Xr0 = u[0] + u[1] + u[2] + u[3] + u[4];
    float Xr2 = u[0], Xi2 = 0.f, Xr4 = u[0], Xi4 = 0.f;
    #pragma unroll
    for (int s = 1; s < 5; ++s) {
        Xr2 += ctC(2 * s) * u[s];  Xi2 -= ctS(2 * s) * u[s];
        Xr4 += ctC(4 * s) * u[s];  Xi4 -= ctS(4 * s) * u[s];
    }
    float Xr1 = v[0], Xi1 = 0.f, Xr3 = v[0], Xi3 = 0.f;
    #pragma unroll
    for (int s = 1; s < 5; ++s) {
        Xr1 += ctC(1 * s) * v[s];  Xi1 -= ctS(1 * s) * v[s];
        Xr3 += ctC(3 * s) * v[s];  Xi3 -= ctS(3 * s) * v[s];
    }
    float Xr5 = v[0] - v[1] + v[2] - v[3] + v[4];

    const float a1 = w0.z, b1 = w0.w;
    const float a2 = w1.x, b2 = w1.y;
    const float a3 = w1.z, b3 = w1.w;
    const float a4 = w2.x, b4 = w2.y;
    const float Zr0 = 0.1f * (Xr0 * w0.x);
    const float Zr5 = 0.1f * (Xr5 * w2.z);
    const float zr1 = 0.2f * (Xr1 * a1 - Xi1 * b1);
    const float zi1 = 0.2f * (Xr1 * b1 + Xi1 * a1);
    const float zr2 = 0.2f * (Xr2 * a2 - Xi2 * b2);
    const float zi2 = 0.2f * (Xr2 * b2 + Xi2 * a2);
    const float zr3 = 0.2f * (Xr3 * a3 - Xi3 * b3);
    const float zi3 = 0.2f * (Xr3 * b3 + Xi3 * a3);
    const float zr4 = 0.2f * (Xr4 * a4 - Xi4 * b4);
    const float zi4 = 0.2f * (Xr4 * b4 + Xi4 * a4);

    #pragma unroll
    for (int t = 0; t < 5; ++t) {
        float E = Zr0
                + zr2 * ctC(2 * t) - zi2 * ctS(2 * t)
                + zr4 * ctC(4 * t) - zi4 * ctS(4 * t);
        float O = ((t & 1) ? -Zr5 : Zr5)
                + zr1 * ctC(t)     - zi1 * ctS(t)
                + zr3 * ctC(3 * t) - zi3 * ctS(3 * t);
        yv[t]     = E + O;
        yv[t + 5] = E - O;
    }
}

// process one row stored at sx[ridx*10 .. ridx*10+10)
__device__ __forceinline__ void process_row(float* sx, int ridx,
                                            const float* __restrict__ w, int d)
{
    const float4* wp = reinterpret_cast<const float4*>(w + d * 12);
    const float4 w0 = wp[0];
    const float4 w1 = wp[1];
    const float4 w2 = wp[2];

    float xv[NPTS], yv[NPTS];
    const float2* s2 = reinterpret_cast<const float2*>(sx);
    #pragma unroll
    for (int i = 0; i < 5; ++i) {
        float2 p = s2[ridx * 5 + i];
        xv[2 * i] = p.x; xv[2 * i + 1] = p.y;
    }
    dft10(xv, yv, w0, w1, w2);
    float2* s2w = reinterpret_cast<float2*>(sx);
    #pragma unroll
    for (int i = 0; i < 5; ++i) {
        float2 p; p.x = yv[2 * i]; p.y = yv[2 * i + 1];
        s2w[ridx * 5 + i] = p;
    }
}

__global__ __launch_bounds__(THREADS)
void global_filter_kernel(const float* __restrict__ x,
                          const float* __restrict__ w,
                          float* __restrict__ y,
                          int n_rows, int dim, int dim_mask)
{
    __shared__ float sx[ROWS_PER_BLOCK * NPTS];   // 20480 B

    const int tid  = threadIdx.x;
    const int wid  = tid >> 5;
    const int lane = tid & 31;
    const int row0 = blockIdx.x * ROWS_PER_BLOCK;
    const int rows_here = min(ROWS_PER_BLOCK, n_rows - row0);

    if (rows_here == ROWS_PER_BLOCK) {
        // ---- warp-autonomous path: no block barriers ----
        const int wrow0 = row0 + wid * WARP_ROWS;        // warp's first row
        float* ws = sx + wid * WARP_ELEMS;               // warp's smem region
        const uint32_t wsb = (uint32_t)__cvta_generic_to_shared(ws);
        const uint64_t pol = make_evict_first_policy();

        // stage in: 5 cp.async per lane, evict_first + 256B granule
        const float4* g = reinterpret_cast<const float4*>(x) +
                          (long long)wrow0 * NPTS / 4;
        #pragma unroll
        for (int i = 0; i < 5; ++i)
            cp_async16_stream(wsb + (uint32_t)(lane + i * 32) * 16u,
                              g + lane + i * 32, pol);
        CPA_COMMIT();
        CPA_WAIT0();
        __syncwarp();

        // compute: 2 rows per lane (rows lane and lane+32 within warp tile)
        const int rA = wrow0 + lane;
        const int rB = rA + 32;
        const int dA = (dim_mask >= 0) ? (rA & dim_mask) : (rA % dim);
        const int dB = (dim_mask >= 0) ? (rB & dim_mask) : (rB % dim);
        process_row(ws, lane,      w, dA);
        process_row(ws, lane + 32, w, dB);
        __syncwarp();

        // stage out: streaming (evict-first) float4 stores
        float4* gy = reinterpret_cast<float4*>(y) +
                     (long long)wrow0 * NPTS / 4;
        const float4* s4 = reinterpret_cast<const float4*>(ws);
        #pragma unroll
        for (int i = 0; i < 5; ++i)
            __stcs(gy + lane + i * 32, s4[lane + i * 32]);
    } else {
        // ---- tail block: straight from global, scalar ----
        for (int rr = tid; rr < rows_here; rr += THREADS) {
            const int row = row0 + rr;
            const long long rb = (long long)row * NPTS;
            const int d = (dim_mask >= 0) ? (row & dim_mask) : (row % dim);
            const float4* wp = reinterpret_cast<const float4*>(w + d * 12);
            float xv[NPTS], yv[NPTS];
            #pragma unroll
            for (int i = 0; i < NPTS; ++i) xv[i] = x[rb + i];
            dft10(xv, yv, wp[0], wp[1], wp[2]);
            #pragma unroll
            for (int i = 0; i < NPTS; ++i) y[rb + i] = yv[i];
        }
    }
}

extern "C" void kernel_launch(void* const* d_in, const int* in_sizes, int n_in,
                              void* d_out, int out_size)
{
    const float* x = (const float*)d_in[0];
    const float* w = (const float*)d_in[1];
    float* y = (float*)d_out;

    const int n_rows = in_sizes[0] / NPTS;       // B * DIM
    const int dim    = in_sizes[1] / 12;         // DIM
    const int dim_mask = ((dim & (dim - 1)) == 0) ? (dim - 1) : -1;

    const int blocks = (n_rows + ROWS_PER_BLOCK - 1) / ROWS_PER_BLOCK;
    global_filter_kernel<<<blocks, THREADS>>>(x, w, y, n_rows, dim, dim_mask);
}